// round 15
// baseline (speedup 1.0000x reference)
#include <cuda_runtime.h>
#include <cstdint>

// SinusoidPositionEncoding: out[b,s,:] = sum_m x[b,s,m] * pe[m,:]
// x one-hot over m (4096). Early-exit prefix scan, 2 rows/warp, 2KB chunks
// (R9 trunk: best ncu 29.6us @ 5.31 TB/s, 60 regs, occ 38%).
// R15 = R14 resubmitted (broker flake, not the kernel). Single change vs R9:
// __launch_bounds__(128,10) caps regs at 51 -> ~40 resident warps/SM (62% occ).
// Across R1-R13, rate tracks occupancy once MLP/warp >= 8 (R1/R2 at occ
// 66-87% hit 6.08 TB/s; all 26-45%-occ variants sit at 4.8-5.3 TB/s).
// Bytes unchanged (~157 MB, confirmed every round).
// x (8,2048,4096) f32, pe (4096,128) f32, out (8,2048,128) f32.

#define N_ROWS (8 * 2048)   // 16384
#define M_VEC  1024         // 4096/4 float4 per row
#define D_VEC  32           // 128/4
#define CHUNK_LOADS 4       // 4 x LDG.128 per lane per chunk = 512 floats
#define N_CHUNKS 8
#define WARPS_PER_BLOCK 4   // 128 threads
#define ROWS_PER_BLOCK (WARPS_PER_BLOCK * 2)   // 8

__device__ __forceinline__ void gather_pe(const float4* __restrict__ pe,
                                          unsigned mask, int hitpos, uint4 hitv,
                                          int lane, float4& acc) {
    while (mask) {
        const int src = __ffs(mask) - 1;
        mask &= mask - 1;
        const int   p  = __shfl_sync(0xffffffffu, hitpos, src);
        const float vx = __uint_as_float(__shfl_sync(0xffffffffu, hitv.x, src));
        const float vy = __uint_as_float(__shfl_sync(0xffffffffu, hitv.y, src));
        const float vz = __uint_as_float(__shfl_sync(0xffffffffu, hitv.z, src));
        const float vw = __uint_as_float(__shfl_sync(0xffffffffu, hitv.w, src));
        const int e = p * 4;
        if (__float_as_uint(vx) != 0u) {
            const float4 pr = __ldg(&pe[(size_t)(e + 0) * D_VEC + lane]);
            acc.x += vx * pr.x; acc.y += vx * pr.y; acc.z += vx * pr.z; acc.w += vx * pr.w;
        }
        if (__float_as_uint(vy) != 0u) {
            const float4 pr = __ldg(&pe[(size_t)(e + 1) * D_VEC + lane]);
            acc.x += vy * pr.x; acc.y += vy * pr.y; acc.z += vy * pr.z; acc.w += vy * pr.w;
        }
        if (__float_as_uint(vz) != 0u) {
            const float4 pr = __ldg(&pe[(size_t)(e + 2) * D_VEC + lane]);
            acc.x += vz * pr.x; acc.y += vz * pr.y; acc.z += vz * pr.z; acc.w += vz * pr.w;
        }
        if (__float_as_uint(vw) != 0u) {
            const float4 pr = __ldg(&pe[(size_t)(e + 3) * D_VEC + lane]);
            acc.x += vw * pr.x; acc.y += vw * pr.y; acc.z += vw * pr.z; acc.w += vw * pr.w;
        }
    }
}

__global__ __launch_bounds__(128, 10)
void pe_onehot_gather2_hiocc_kernel(const uint4* __restrict__ x,
                                    const float4* __restrict__ pe,
                                    float4* __restrict__ out) {
    const int warp = threadIdx.x >> 5;
    const int lane = threadIdx.x & 31;
    // Block owns 8 contiguous rows; warp w owns rows base+w and base+w+4.
    const int rowA = blockIdx.x * ROWS_PER_BLOCK + warp;
    const int rowB = rowA + WARPS_PER_BLOCK;

    const uint4* xA = x + (size_t)rowA * M_VEC;
    const uint4* xB = x + (size_t)rowB * M_VEC;

    uint4 hvA = make_uint4(0u,0u,0u,0u), hvB = make_uint4(0u,0u,0u,0u);
    int hpA = -1, hpB = -1;
    unsigned ballA = 0u, ballB = 0u;

    for (int c = 0; c < N_CHUNKS; c++) {
        const int base = c * (CHUNK_LOADS * 32);
        const bool actA = (ballA == 0u);   // warp-uniform
        const bool actB = (ballB == 0u);   // warp-uniform
        uint4 vA[CHUNK_LOADS], vB[CHUNK_LOADS];

        if (actA) {
            #pragma unroll
            for (int j = 0; j < CHUNK_LOADS; j++)
                vA[j] = __ldcs(&xA[base + j * 32 + lane]);
        }
        if (actB) {
            #pragma unroll
            for (int j = 0; j < CHUNK_LOADS; j++)
                vB[j] = __ldcs(&xB[base + j * 32 + lane]);
        }
        if (actA) {
            #pragma unroll
            for (int j = 0; j < CHUNK_LOADS; j++)
                if ((vA[j].x | vA[j].y | vA[j].z | vA[j].w) != 0u) {
                    hvA = vA[j]; hpA = base + j * 32 + lane;
                }
            ballA = __ballot_sync(0xffffffffu, hpA >= 0);
        }
        if (actB) {
            #pragma unroll
            for (int j = 0; j < CHUNK_LOADS; j++)
                if ((vB[j].x | vB[j].y | vB[j].z | vB[j].w) != 0u) {
                    hvB = vB[j]; hpB = base + j * 32 + lane;
                }
            ballB = __ballot_sync(0xffffffffu, hpB >= 0);
        }
        if (ballA && ballB) break;
    }

    float4 accA = make_float4(0.f,0.f,0.f,0.f);
    float4 accB = make_float4(0.f,0.f,0.f,0.f);
    gather_pe(pe, ballA, hpA, hvA, lane, accA);
    gather_pe(pe, ballB, hpB, hvB, lane, accB);

    __stcs(&out[(size_t)rowA * D_VEC + lane], accA);
    __stcs(&out[(size_t)rowB * D_VEC + lane], accB);
}

extern "C" void kernel_launch(void* const* d_in, const int* in_sizes, int n_in,
                              void* d_out, int out_size) {
    const uint4*  x  = (const uint4*)d_in[0];    // (8,2048,4096) f32
    const float4* pe = (const float4*)d_in[1];   // (4096,128)    f32
    float4* out = (float4*)d_out;                // (8,2048,128)  f32

    const int grid = N_ROWS / ROWS_PER_BLOCK;    // 2048 blocks of 128 threads
    pe_onehot_gather2_hiocc_kernel<<<grid, 128>>>(x, pe, out);
}

// round 17
// speedup vs baseline: 1.0656x; 1.0656x over previous
#include <cuda_runtime.h>
#include <cstdint>

// SinusoidPositionEncoding: out[b,s,:] = sum_m x[b,s,m] * pe[m,:]
// x one-hot over m (4096). Early-exit prefix scan, 2 rows/warp, 2KB chunks
// (R9 trunk). R17 = R16 resubmitted (broker flake). DEFERRED hit extraction:
// scan loop does only OR-reduce + ballot per row (hit chunk's data stays in
// registers, since the act-guard stops reloads after the hit); (hitpos,hitval)
// extracted once after the loop. ~40% less scan ALU, ~50 natural regs (R15
// showed forcing 48 via launch_bounds spills the hit-tracking state; this
// removes that state). x (8,2048,4096) f32, pe (4096,128) f32,
// out (8,2048,128) f32.

#define N_ROWS (8 * 2048)   // 16384
#define M_VEC  1024         // 4096/4 float4 per row
#define D_VEC  32           // 128/4
#define CL 4                // 4 x LDG.128 per lane per chunk = 512 floats
#define CHUNK_V (CL * 32)   // 128 float4 per chunk
#define N_CHUNKS 8
#define WARPS_PER_BLOCK 4   // 128 threads
#define ROWS_PER_BLOCK (WARPS_PER_BLOCK * 2)   // 8

__device__ __forceinline__ void gather_pe(const float4* __restrict__ pe,
                                          unsigned mask, int hitpos, uint4 hitv,
                                          int lane, float4& acc) {
    while (mask) {
        const int src = __ffs(mask) - 1;
        mask &= mask - 1;
        const int   p  = __shfl_sync(0xffffffffu, hitpos, src);
        const float vx = __uint_as_float(__shfl_sync(0xffffffffu, hitv.x, src));
        const float vy = __uint_as_float(__shfl_sync(0xffffffffu, hitv.y, src));
        const float vz = __uint_as_float(__shfl_sync(0xffffffffu, hitv.z, src));
        const float vw = __uint_as_float(__shfl_sync(0xffffffffu, hitv.w, src));
        const int e = p * 4;
        if (__float_as_uint(vx) != 0u) {
            const float4 pr = __ldg(&pe[(size_t)(e + 0) * D_VEC + lane]);
            acc.x += vx * pr.x; acc.y += vx * pr.y; acc.z += vx * pr.z; acc.w += vx * pr.w;
        }
        if (__float_as_uint(vy) != 0u) {
            const float4 pr = __ldg(&pe[(size_t)(e + 1) * D_VEC + lane]);
            acc.x += vy * pr.x; acc.y += vy * pr.y; acc.z += vy * pr.z; acc.w += vy * pr.w;
        }
        if (__float_as_uint(vz) != 0u) {
            const float4 pr = __ldg(&pe[(size_t)(e + 2) * D_VEC + lane]);
            acc.x += vz * pr.x; acc.y += vz * pr.y; acc.z += vz * pr.z; acc.w += vz * pr.w;
        }
        if (__float_as_uint(vw) != 0u) {
            const float4 pr = __ldg(&pe[(size_t)(e + 3) * D_VEC + lane]);
            acc.x += vw * pr.x; acc.y += vw * pr.y; acc.z += vw * pr.z; acc.w += vw * pr.w;
        }
    }
}

// OR-reduce a 4 x uint4 chunk buffer to one word.
__device__ __forceinline__ unsigned or16(const uint4* v) {
    unsigned o = 0u;
    #pragma unroll
    for (int j = 0; j < CL; j++)
        o |= v[j].x | v[j].y | v[j].z | v[j].w;
    return o;
}

// After the scan: find (hitpos, hitval) inside the preserved chunk buffer.
__device__ __forceinline__ void extract_hit(const uint4* v, int chunk, int lane,
                                            int& hp, uint4& hv) {
    #pragma unroll
    for (int j = 0; j < CL; j++)
        if ((v[j].x | v[j].y | v[j].z | v[j].w) != 0u) {
            hv = v[j];
            hp = chunk * CHUNK_V + j * 32 + lane;
        }
}

__global__ __launch_bounds__(128)
void pe_onehot_defer_kernel(const uint4* __restrict__ x,
                            const float4* __restrict__ pe,
                            float4* __restrict__ out) {
    const int warp = threadIdx.x >> 5;
    const int lane = threadIdx.x & 31;
    // Block owns 8 contiguous rows; warp w owns rows base+w and base+w+4.
    const int rowA = blockIdx.x * ROWS_PER_BLOCK + warp;
    const int rowB = rowA + WARPS_PER_BLOCK;

    const uint4* xA = x + (size_t)rowA * M_VEC;
    const uint4* xB = x + (size_t)rowB * M_VEC;

    uint4 vA[CL], vB[CL];
    unsigned ballA = 0u, ballB = 0u;
    int cA = 0, cB = 0;   // chunk index at which each row's ballot fired

    for (int c = 0; c < N_CHUNKS; c++) {
        const int base = c * CHUNK_V;
        const bool actA = (ballA == 0u);   // warp-uniform
        const bool actB = (ballB == 0u);   // warp-uniform

        if (actA) {
            #pragma unroll
            for (int j = 0; j < CL; j++)
                vA[j] = __ldcs(&xA[base + j * 32 + lane]);
        }
        if (actB) {
            #pragma unroll
            for (int j = 0; j < CL; j++)
                vB[j] = __ldcs(&xB[base + j * 32 + lane]);
        }
        if (actA) {
            ballA = __ballot_sync(0xffffffffu, or16(vA) != 0u);
            cA = c;                         // == hit chunk when ballA fires
        }
        if (actB) {
            ballB = __ballot_sync(0xffffffffu, or16(vB) != 0u);
            cB = c;
        }
        if (ballA && ballB) break;
    }

    // Deferred extraction: hit data still lives in the preserved buffers.
    int hpA = -1, hpB = -1;
    uint4 hvA = make_uint4(0u,0u,0u,0u), hvB = make_uint4(0u,0u,0u,0u);
    if (ballA) extract_hit(vA, cA, lane, hpA, hvA);
    if (ballB) extract_hit(vB, cB, lane, hpB, hvB);

    float4 accA = make_float4(0.f,0.f,0.f,0.f);
    float4 accB = make_float4(0.f,0.f,0.f,0.f);
    gather_pe(pe, ballA, hpA, hvA, lane, accA);
    gather_pe(pe, ballB, hpB, hvB, lane, accB);

    __stcs(&out[(size_t)rowA * D_VEC + lane], accA);
    __stcs(&out[(size_t)rowB * D_VEC + lane], accB);
}

extern "C" void kernel_launch(void* const* d_in, const int* in_sizes, int n_in,
                              void* d_out, int out_size) {
    const uint4*  x  = (const uint4*)d_in[0];    // (8,2048,4096) f32
    const float4* pe = (const float4*)d_in[1];   // (4096,128)    f32
    float4* out = (float4*)d_out;                // (8,2048,128)  f32

    const int grid = N_ROWS / ROWS_PER_BLOCK;    // 2048 blocks of 128 threads
    pe_onehot_defer_kernel<<<grid, 128>>>(x, pe, out);
}